// round 1
// baseline (speedup 1.0000x reference)
#include <cuda_runtime.h>

#define D_DIM   512
#define H1_DIM  128
#define H2_DIM  64
#define B_DIM   2048
#define N_NODES 20000
#define N_DRUG  2000

// Scratch: layer-1 partial products (allowed: __device__ globals, no alloc)
__device__ float g_Ptop[N_DRUG  * H1_DIM];   // embed[:2000]  @ W1[0:512]    (1 MB)
__device__ float g_Pbot[N_NODES * H1_DIM];   // embed[:20000] @ W1[512:1024] (10 MB)

// ---------------------------------------------------------------------------
// Kernel 1: P[r][o] = sum_d embed[r][d] * W1[woff+d][o]
// Tile: 32 rows x 128 cols, BK=16, 256 threads, 4x4 micro-tile.
// Grid: 625 "bot" blocks + 63 "top" blocks = 688 (load-balanced, ~4.6/SM).
// ---------------------------------------------------------------------------
__global__ void __launch_bounds__(256) gemm1_kernel(const float* __restrict__ embed,
                                                    const float* __restrict__ W1) {
    const int NBOT = (N_NODES + 31) / 32;   // 625
    int bx = blockIdx.x;
    int woff, M;
    float* P;
    if (bx < NBOT) { woff = D_DIM; M = N_NODES; P = g_Pbot; }
    else           { bx -= NBOT; woff = 0; M = N_DRUG; P = g_Ptop; }
    const int row0 = bx * 32;

    __shared__ float As[16][32];    // k-major A tile
    __shared__ float Bs[16][128];   // k-major B tile (W1 layout)

    const int tid = threadIdx.x;
    const int tx = tid & 31;        // 32 col-groups of 4
    const int ty = tid >> 5;        // 8 row-groups of 4

    float acc[4][4];
#pragma unroll
    for (int i = 0; i < 4; i++)
#pragma unroll
        for (int j = 0; j < 4; j++) acc[i][j] = 0.f;

    for (int k0 = 0; k0 < D_DIM; k0 += 16) {
        // Load A tile: 32 rows x 16 cols (128 threads, float4 each)
        if (tid < 128) {
            int r = tid >> 2;              // 0..31
            int c = (tid & 3) << 2;        // 0,4,8,12
            int gr = min(row0 + r, M - 1); // clamp (reads valid, extra rows discarded)
            float4 v = *(const float4*)&embed[gr * D_DIM + k0 + c];
            As[c + 0][r] = v.x; As[c + 1][r] = v.y;
            As[c + 2][r] = v.z; As[c + 3][r] = v.w;
        }
        // Load B tile: 16 rows x 128 cols (256 threads, 2 float4 each)
#pragma unroll
        for (int p = 0; p < 2; p++) {
            int kk = (tid >> 5) + p * 8;         // 0..15
            int cc = (tid & 31) << 2;            // 0..124
            float4 v = *(const float4*)&W1[(woff + k0 + kk) * H1_DIM + cc];
            *(float4*)&Bs[kk][cc] = v;
        }
        __syncthreads();

#pragma unroll
        for (int k = 0; k < 16; k++) {
            float4 av = *(const float4*)&As[k][ty << 2];  // broadcast within warp
            float4 bv = *(const float4*)&Bs[k][tx << 2];
            float a[4] = {av.x, av.y, av.z, av.w};
            float b[4] = {bv.x, bv.y, bv.z, bv.w};
#pragma unroll
            for (int i = 0; i < 4; i++)
#pragma unroll
                for (int j = 0; j < 4; j++)
                    acc[i][j] = fmaf(a[i], b[j], acc[i][j]);
        }
        __syncthreads();
    }

#pragma unroll
    for (int i = 0; i < 4; i++) {
        int r = row0 + (ty << 2) + i;
        if (r < M) {
            float4 v = make_float4(acc[i][0], acc[i][1], acc[i][2], acc[i][3]);
            *(float4*)&P[r * H1_DIM + (tx << 2)] = v;
        }
    }
}

// ---------------------------------------------------------------------------
// Kernel 2: per block, 64 global samples.
//   sample S: b = S/65, r = S%65
//     r<32  : neg1  -> i=h[b],        j=n_s[b][r],  out[2048 + b*64 + r]
//     32<=r<64: neg2 -> i=n_s[b][r],  j=t[b],       out[2048 + b*64 + r]
//     r==64 : pos   -> i=h[b],        j=t[b],       out[b]
//   x1 = relu(Ptop[i] + Pbot[j] + b1)  (64 x 128 in smem)
//   h2 = x1 @ W2   (register-blocked 4x4, W2 in smem)
//   out = relu(h2 + b2) @ W3 + b3     (shfl reduction over 16 lanes)
// ---------------------------------------------------------------------------
#define SMEM2_FLOATS (64 * 132 + 128 * 64 + 128 + 64 + 64)
#define SMEM2_BYTES  (SMEM2_FLOATS * 4 + 3 * 64 * 4)

__global__ void __launch_bounds__(256) mlp2_kernel(
    const int* __restrict__ h, const int* __restrict__ t, const int* __restrict__ ns,
    const float* __restrict__ b1, const float* __restrict__ W2,
    const float* __restrict__ b2, const float* __restrict__ W3,
    const float* __restrict__ b3, float* __restrict__ out)
{
    extern __shared__ float smem[];
    float* X1  = smem;                 // [64][132]
    float* W2s = X1 + 64 * 132;        // [128][64] (k-major, same as global)
    float* b1s = W2s + 128 * 64;       // [128]
    float* b2s = b1s + 128;            // [64]
    float* W3s = b2s + 64;             // [64]
    int* sTop = (int*)(W3s + 64);      // [64]
    int* sBot = sTop + 64;             // [64]
    int* sOut = sBot + 64;             // [64]

    const int tid = threadIdx.x;

    // ---- phase 0: decode sample indices + stage small tensors ----
    if (tid < 64) {
        int S = blockIdx.x * 64 + tid;
        int b = S / 65;
        int r = S - b * 65;
        int itop, jbot, oaddr;
        if (r == 64)      { itop = h[b];           jbot = t[b];           oaddr = b; }
        else if (r < 32)  { itop = h[b];           jbot = ns[b * 64 + r]; oaddr = B_DIM + b * 64 + r; }
        else              { itop = ns[b * 64 + r]; jbot = t[b];           oaddr = B_DIM + b * 64 + r; }
        sTop[tid] = itop; sBot[tid] = jbot; sOut[tid] = oaddr;
    }
#pragma unroll
    for (int i = tid; i < 2048; i += 256)   // W2: 8192 floats = 2048 float4
        ((float4*)W2s)[i] = ((const float4*)W2)[i];
    if (tid < 128) b1s[tid] = b1[tid];
    if (tid < 64) { b2s[tid] = b2[tid]; W3s[tid] = W3[tid]; }
    __syncthreads();

    // ---- phase 1: build X1 (one warp per sample per iteration) ----
    {
        const int lane = tid & 31;
        const int wid = tid >> 5;
        float4 vb1 = *(const float4*)&b1s[lane << 2];
#pragma unroll
        for (int it = 0; it < 8; it++) {
            int s = it * 8 + wid;
            int i = sTop[s], j = sBot[s];
            float4 pa = *(const float4*)&g_Ptop[i * H1_DIM + (lane << 2)];
            float4 pb = *(const float4*)&g_Pbot[j * H1_DIM + (lane << 2)];
            float4 x;
            x.x = fmaxf(pa.x + pb.x + vb1.x, 0.f);
            x.y = fmaxf(pa.y + pb.y + vb1.y, 0.f);
            x.z = fmaxf(pa.z + pb.z + vb1.z, 0.f);
            x.w = fmaxf(pa.w + pb.w + vb1.w, 0.f);
            *(float4*)&X1[s * 132 + (lane << 2)] = x;
        }
    }
    __syncthreads();

    // ---- phase 2: [64x128] @ [128x64], 4x4 micro-tile per thread ----
    const int tx = tid & 15;   // output group: cols 4tx..4tx+3
    const int ty = tid >> 4;   // sample group: rows 4ty..4ty+3

    float acc[4][4];
#pragma unroll
    for (int i = 0; i < 4; i++)
#pragma unroll
        for (int j = 0; j < 4; j++) acc[i][j] = 0.f;

    for (int kq = 0; kq < 32; kq++) {
        float4 xa[4], wb[4];
#pragma unroll
        for (int si = 0; si < 4; si++)
            xa[si] = *(const float4*)&X1[(4 * ty + si) * 132 + (kq << 2)];
#pragma unroll
        for (int kk = 0; kk < 4; kk++)
            wb[kk] = *(const float4*)&W2s[((kq << 2) + kk) * H2_DIM + (tx << 2)];
#pragma unroll
        for (int kk = 0; kk < 4; kk++) {
#pragma unroll
            for (int si = 0; si < 4; si++) {
                float x = (kk == 0) ? xa[si].x : (kk == 1) ? xa[si].y
                        : (kk == 2) ? xa[si].z : xa[si].w;
                acc[si][0] = fmaf(x, wb[kk].x, acc[si][0]);
                acc[si][1] = fmaf(x, wb[kk].y, acc[si][1]);
                acc[si][2] = fmaf(x, wb[kk].z, acc[si][2]);
                acc[si][3] = fmaf(x, wb[kk].w, acc[si][3]);
            }
        }
    }

    // ---- phase 3: layer 3 + reduction over the 16 tx groups ----
    float4 b2r = *(const float4*)&b2s[tx << 2];
    float4 w3r = *(const float4*)&W3s[tx << 2];
    const float b3v = b3[0];

#pragma unroll
    for (int si = 0; si < 4; si++) {
        float p = 0.f;
        float v;
        v = fmaxf(acc[si][0] + b2r.x, 0.f); p = fmaf(v, w3r.x, p);
        v = fmaxf(acc[si][1] + b2r.y, 0.f); p = fmaf(v, w3r.y, p);
        v = fmaxf(acc[si][2] + b2r.z, 0.f); p = fmaf(v, w3r.z, p);
        v = fmaxf(acc[si][3] + b2r.w, 0.f); p = fmaf(v, w3r.w, p);
#pragma unroll
        for (int m = 8; m > 0; m >>= 1)
            p += __shfl_xor_sync(0xffffffffu, p, m, 16);
        if (tx == 0)
            out[sOut[4 * ty + si]] = p + b3v;
    }
}

// ---------------------------------------------------------------------------
extern "C" void kernel_launch(void* const* d_in, const int* in_sizes, int n_in,
                              void* d_out, int out_size) {
    const float* embed = (const float*)d_in[0];
    const float* W1    = (const float*)d_in[1];
    const float* b1    = (const float*)d_in[2];
    const float* W2    = (const float*)d_in[3];
    const float* b2    = (const float*)d_in[4];
    const float* W3    = (const float*)d_in[5];
    const float* b3    = (const float*)d_in[6];
    const int*   h     = (const int*)d_in[7];
    const int*   t     = (const int*)d_in[8];
    const int*   ns    = (const int*)d_in[9];
    float* out = (float*)d_out;

    const int NBOT = (N_NODES + 31) / 32;   // 625
    const int NTOP = (N_DRUG  + 31) / 32;   // 63
    gemm1_kernel<<<NBOT + NTOP, 256>>>(embed, W1);

    cudaFuncSetAttribute(mlp2_kernel, cudaFuncAttributeMaxDynamicSharedMemorySize,
                         SMEM2_BYTES);
    mlp2_kernel<<<(B_DIM * 65) / 64, 256, SMEM2_BYTES>>>(h, t, ns, b1, W2, b2, W3, b3, out);
}

// round 2
// speedup vs baseline: 1.1605x; 1.1605x over previous
#include <cuda_runtime.h>

#define D_DIM   512
#define H1_DIM  128
#define H2_DIM  64
#define B_DIM   2048
#define N_NODES 20000
#define N_DRUG  2000

typedef unsigned long long ull;

__device__ __forceinline__ ull pack2s(float x) {            // {x, x}
    ull r; asm("mov.b64 %0, {%1, %1};" : "=l"(r) : "f"(x)); return r;
}
__device__ __forceinline__ void ffma2(ull& d, ull a, ull b) { // d += a*b (2-lane)
    asm("fma.rn.f32x2 %0, %1, %2, %3;" : "=l"(d) : "l"(a), "l"(b), "l"(d));
}
__device__ __forceinline__ float2 unpk(ull v) {
    float2 f; asm("mov.b64 {%0, %1}, %2;" : "=f"(f.x), "=f"(f.y) : "l"(v)); return f;
}

// Scratch: layer-1 partial products
__device__ float g_Ptop[N_DRUG  * H1_DIM];   // embed[:2000]  @ W1[0:512]
__device__ float g_Pbot[N_NODES * H1_DIM];   // embed[:20000] @ W1[512:1024]

// ---------------------------------------------------------------------------
// Kernel 1: P[r][o] = sum_d embed[r][d] * W1[woff+d][o]
// Tile: 64 rows x 128 cols, BK=16, 256 threads, 8x4 micro-tile, FFMA2 packed
// over column pairs. Grid: 313 bot + 32 top = 345 blocks.
// ---------------------------------------------------------------------------
#define AS_STRIDE 68   // padded: float4-aligned (68*4B=272B=17*16B), 2-way STS conflict only

__global__ void __launch_bounds__(256) gemm1_kernel(const float* __restrict__ embed,
                                                    const float* __restrict__ W1) {
    const int NBOT = (N_NODES + 63) / 64;   // 313
    int bx = blockIdx.x;
    int woff, M;
    float* P;
    if (bx < NBOT) { woff = D_DIM; M = N_NODES; P = g_Pbot; }
    else           { bx -= NBOT; woff = 0; M = N_DRUG; P = g_Ptop; }
    const int row0 = bx * 64;

    __shared__ float As[16 * AS_STRIDE];   // k-major [16][64(+pad)]
    __shared__ float Bs[16 * 128];         // k-major [16][128]

    const int tid = threadIdx.x;
    const int tx = tid & 31;        // 32 col-groups of 4  -> 128 cols
    const int ty = tid >> 5;        // 8 row-groups of 8   -> 64 rows (warp-uniform)

    ull acc[8][2];
#pragma unroll
    for (int i = 0; i < 8; i++) { acc[i][0] = 0ull; acc[i][1] = 0ull; }

    // A-load assignment (per k0 tile): thread -> (row r, 4 k's at c)
    const int ar = tid >> 2;              // 0..63
    const int ac = (tid & 3) << 2;        // 0,4,8,12
    const int agr = min(row0 + ar, M - 1);

    for (int k0 = 0; k0 < D_DIM; k0 += 16) {
        // A tile: 64 rows x 16 k (transposed store, 2-way conflict w/ pad 68)
        {
            float4 v = *(const float4*)&embed[agr * D_DIM + k0 + ac];
            As[(ac + 0) * AS_STRIDE + ar] = v.x;
            As[(ac + 1) * AS_STRIDE + ar] = v.y;
            As[(ac + 2) * AS_STRIDE + ar] = v.z;
            As[(ac + 3) * AS_STRIDE + ar] = v.w;
        }
        // B tile: 16 k x 128 cols (conflict-free float4)
#pragma unroll
        for (int p = 0; p < 2; p++) {
            int kk = ty + p * 8;
            int cc = tx << 2;
            *(float4*)&Bs[kk * 128 + cc] =
                *(const float4*)&W1[(woff + k0 + kk) * H1_DIM + cc];
        }
        __syncthreads();

#pragma unroll
        for (int k = 0; k < 16; k++) {
            const float4 a0 = *(const float4*)&As[k * AS_STRIDE + ty * 8];
            const float4 a1 = *(const float4*)&As[k * AS_STRIDE + ty * 8 + 4];
            const ulonglong2 bb = *(const ulonglong2*)&Bs[k * 128 + (tx << 2)];
            ull ap[8];
            ap[0] = pack2s(a0.x); ap[1] = pack2s(a0.y);
            ap[2] = pack2s(a0.z); ap[3] = pack2s(a0.w);
            ap[4] = pack2s(a1.x); ap[5] = pack2s(a1.y);
            ap[6] = pack2s(a1.z); ap[7] = pack2s(a1.w);
#pragma unroll
            for (int i = 0; i < 8; i++) {
                ffma2(acc[i][0], ap[i], bb.x);
                ffma2(acc[i][1], ap[i], bb.y);
            }
        }
        __syncthreads();
    }

#pragma unroll
    for (int i = 0; i < 8; i++) {
        int r = row0 + ty * 8 + i;
        if (r < M) {
            float2 c01 = unpk(acc[i][0]);
            float2 c23 = unpk(acc[i][1]);
            *(float4*)&P[r * H1_DIM + (tx << 2)] =
                make_float4(c01.x, c01.y, c23.x, c23.y);
        }
    }
}

// ---------------------------------------------------------------------------
// Kernel 2: 128 samples per block, 256 threads, 8x4 micro-tile, FFMA2 packed.
//   sample S: b = S/65, r = S%65
//     r<32   : neg1 -> i=h[b],       j=ns[b][r],  out[2048 + b*64 + r]
//     32<=r<64: neg2 -> i=ns[b][r],  j=t[b],      out[2048 + b*64 + r]
//     r==64  : pos  -> i=h[b],       j=t[b],      out[b]
// ---------------------------------------------------------------------------
#define NSAMP 128
#define X1_STRIDE 132
#define SMEM2_BYTES ((NSAMP * X1_STRIDE + 128 * 64 + 128 + 64 + 64) * 4 + 3 * NSAMP * 4)

__global__ void __launch_bounds__(256) mlp2_kernel(
    const int* __restrict__ h, const int* __restrict__ t, const int* __restrict__ ns,
    const float* __restrict__ b1, const float* __restrict__ W2,
    const float* __restrict__ b2, const float* __restrict__ W3,
    const float* __restrict__ b3, float* __restrict__ out)
{
    extern __shared__ float smem[];
    float* X1  = smem;                       // [128][132]
    float* W2s = X1 + NSAMP * X1_STRIDE;     // [128][64] k-major
    float* b1s = W2s + 128 * 64;             // [128]
    float* b2s = b1s + 128;                  // [64]
    float* W3s = b2s + 64;                   // [64]
    int* sTop = (int*)(W3s + 64);            // [128]
    int* sBot = sTop + NSAMP;                // [128]
    int* sOut = sBot + NSAMP;                // [128]

    const int tid = threadIdx.x;

    // ---- phase 0: decode sample indices + stage small tensors ----
    if (tid < NSAMP) {
        int S = blockIdx.x * NSAMP + tid;
        int b = S / 65;
        int r = S - b * 65;
        int itop, jbot, oaddr;
        if (r == 64)      { itop = h[b];           jbot = t[b];           oaddr = b; }
        else if (r < 32)  { itop = h[b];           jbot = ns[b * 64 + r]; oaddr = B_DIM + b * 64 + r; }
        else              { itop = ns[b * 64 + r]; jbot = t[b];           oaddr = B_DIM + b * 64 + r; }
        sTop[tid] = itop; sBot[tid] = jbot; sOut[tid] = oaddr;
    }
#pragma unroll
    for (int i = tid; i < 2048; i += 256)   // W2: 8192 floats = 2048 float4
        ((float4*)W2s)[i] = ((const float4*)W2)[i];
    if (tid < 128) b1s[tid] = b1[tid];
    if (tid < 64) { b2s[tid] = b2[tid]; W3s[tid] = W3[tid]; }
    __syncthreads();

    // ---- phase 1: build X1 = relu(Ptop[i] + Pbot[j] + b1), one warp/sample ----
    {
        const int lane = tid & 31;
        const int wid = tid >> 5;
        float4 vb1 = *(const float4*)&b1s[lane << 2];
#pragma unroll
        for (int it = 0; it < NSAMP / 8; it++) {
            int s = it * 8 + wid;
            int i = sTop[s], j = sBot[s];
            float4 pa = *(const float4*)&g_Ptop[i * H1_DIM + (lane << 2)];
            float4 pb = *(const float4*)&g_Pbot[j * H1_DIM + (lane << 2)];
            float4 x;
            x.x = fmaxf(pa.x + pb.x + vb1.x, 0.f);
            x.y = fmaxf(pa.y + pb.y + vb1.y, 0.f);
            x.z = fmaxf(pa.z + pb.z + vb1.z, 0.f);
            x.w = fmaxf(pa.w + pb.w + vb1.w, 0.f);
            *(float4*)&X1[s * X1_STRIDE + (lane << 2)] = x;
        }
    }
    __syncthreads();

    // ---- phase 2: [128x128] @ [128x64], 8x4 micro-tile, FFMA2 ----
    const int tx = tid & 15;   // cols 4tx..4tx+3
    const int ty = tid >> 4;   // samples 8ty..8ty+7

    ull acc[8][2];
#pragma unroll
    for (int i = 0; i < 8; i++) { acc[i][0] = 0ull; acc[i][1] = 0ull; }

#pragma unroll 2
    for (int kq = 0; kq < 32; kq++) {
        float4 xa[8];
#pragma unroll
        for (int si = 0; si < 8; si++)
            xa[si] = *(const float4*)&X1[(8 * ty + si) * X1_STRIDE + (kq << 2)];
#pragma unroll
        for (int kk = 0; kk < 4; kk++) {
            const ulonglong2 w =
                *(const ulonglong2*)&W2s[((kq << 2) + kk) * H2_DIM + (tx << 2)];
#pragma unroll
            for (int si = 0; si < 8; si++) {
                float x = (kk == 0) ? xa[si].x : (kk == 1) ? xa[si].y
                        : (kk == 2) ? xa[si].z : xa[si].w;
                ull xp = pack2s(x);
                ffma2(acc[si][0], xp, w.x);
                ffma2(acc[si][1], xp, w.y);
            }
        }
    }

    // ---- phase 3: layer 3 + reduction over 16 tx groups ----
    float4 b2r = *(const float4*)&b2s[tx << 2];
    float4 w3r = *(const float4*)&W3s[tx << 2];
    const float b3v = b3[0];

#pragma unroll
    for (int si = 0; si < 8; si++) {
        float2 c01 = unpk(acc[si][0]);
        float2 c23 = unpk(acc[si][1]);
        float p = 0.f, v;
        v = fmaxf(c01.x + b2r.x, 0.f); p = fmaf(v, w3r.x, p);
        v = fmaxf(c01.y + b2r.y, 0.f); p = fmaf(v, w3r.y, p);
        v = fmaxf(c23.x + b2r.z, 0.f); p = fmaf(v, w3r.z, p);
        v = fmaxf(c23.y + b2r.w, 0.f); p = fmaf(v, w3r.w, p);
#pragma unroll
        for (int m = 8; m > 0; m >>= 1)
            p += __shfl_xor_sync(0xffffffffu, p, m, 16);
        if (tx == 0)
            out[sOut[8 * ty + si]] = p + b3v;
    }
}

// ---------------------------------------------------------------------------
extern "C" void kernel_launch(void* const* d_in, const int* in_sizes, int n_in,
                              void* d_out, int out_size) {
    const float* embed = (const float*)d_in[0];
    const float* W1    = (const float*)d_in[1];
    const float* b1    = (const float*)d_in[2];
    const float* W2    = (const float*)d_in[3];
    const float* b2    = (const float*)d_in[4];
    const float* W3    = (const float*)d_in[5];
    const float* b3    = (const float*)d_in[6];
    const int*   h     = (const int*)d_in[7];
    const int*   t     = (const int*)d_in[8];
    const int*   ns    = (const int*)d_in[9];
    float* out = (float*)d_out;

    const int NBOT = (N_NODES + 63) / 64;   // 313
    const int NTOP = (N_DRUG  + 63) / 64;   // 32
    gemm1_kernel<<<NBOT + NTOP, 256>>>(embed, W1);

    cudaFuncSetAttribute(mlp2_kernel, cudaFuncAttributeMaxDynamicSharedMemorySize,
                         SMEM2_BYTES);
    mlp2_kernel<<<(B_DIM * 65) / NSAMP, 256, SMEM2_BYTES>>>(h, t, ns, b1, W2, b2, W3, b3, out);
}